// round 7
// baseline (speedup 1.0000x reference)
#include <cuda_runtime.h>

#define NT    64
#define BATCH 8192

// Per sample: E_w = <Phi| (⊗_{j<=w} O_j) |Phi>,  Phi = CNOT-chain |⊗ phi_j>
// (bond-2 MPS).  O_j = cos^2(t) Z + sin(t)cos(t) Y - sin(t) X, t = params[1][j].
// phi_j = RY(t1) RX(t1) RY(x_j)|0>, t1 = params[0][j].
// Hermitian boundary: L00, L11 real, P = L01 complex.
//   A=|f0|^2, B=|f1|^2, g=f0*conj(f1)
//   N00 = A L00 + B L11 + 2(gr Pr - gi Pi)
//   N11 = B L00 + A L11 + 2(gr Pr + gi Pi)
//   N01 = ( gr(L00+L11) + (A+B) Pr ,  gi(L00-L11) + (A-B) Pi )
//   L00' = cc N00,  L11' = -cc N11,  P' = (a + i b) N01
// Emission: E_{j-1} = (L00+L11) + 4 gr_j Pr;  E_11 = L00 + L11 + 2 Pr.
// Uniform param trig is computed once per LANE GROUP and broadcast by SHFL:
//   lane j (<12):   u = cos^2(t1_j/2), w = cos(t1_j/2) sin(t1_j/2)
//   lane 12+j:      Oa = -sin t2_j, Ob = sin t2 cos t2, Oc = cos^2 t2
// f0/f1 in terms of (u,w):  f0r=u cx - w sx, f0i=(1-u)cx - w sx,
//                           f1r=w cx + u sx, f1i=-(1-u)sx - w cx.
__global__ void __launch_bounds__(NT)
qexp_kernel(const float* __restrict__ x, const float* __restrict__ params,
            const float* __restrict__ hw, const float* __restrict__ hb,
            float* __restrict__ out)
{
    const int t    = threadIdx.x;
    const int lane = t & 31;
    const int b    = blockIdx.x * NT + t;

    // ---- issue all loads up front ----
    const float4* xv = (const float4*)(x + b * 12);       // 48B row, 16B aligned
    const float4 xq0 = xv[0], xq1 = xv[1], xq2 = xv[2];
    const float  myp = params[lane < 24 ? lane : 23];     // coalesced 96B, broadcast across warps
    const float4* wv = (const float4*)hw;                 // 12 floats (broadcast)
    const float4 w0 = wv[0], w1 = wv[1], w2 = wv[2];
    const float bias = hb[0];

    const float xa[12]  = { xq0.x,xq0.y,xq0.z,xq0.w, xq1.x,xq1.y,xq1.z,xq1.w,
                            xq2.x,xq2.y,xq2.z,xq2.w };
    const float hwa[12] = { w0.x,w0.y,w0.z,w0.w, w1.x,w1.y,w1.z,w1.w,
                            w2.x,w2.y,w2.z,w2.w };

    // ---- ONE uniform sincos per lane (replaces 24 per thread) ----
    const float ang = (lane < 12) ? 0.5f * myp : myp;
    float sp, cp; __sincosf(ang, &sp, &cp);
    // lane<12 exports (u,w); lane in [12,24) exports (Oa,Ob,Oc)
    const float expA = (lane < 12) ? cp * cp : -sp;        // u        | Oa
    const float expB = (lane < 12) ? cp * sp : sp * cp;    // w        | Ob
    const float expC = cp * cp;                            // (unused) | Oc

    // ---- per-sample x trig (12 sincos, MUFU-pipelined) ----
    float Aq[12], Bq[12], Gr[12], Gi[12], Oa[12], Ob[12], Oc[12];
    #pragma unroll
    for (int j = 0; j < 12; j++){
        const float u  = __shfl_sync(0xffffffffu, expA, j);
        const float w  = __shfl_sync(0xffffffffu, expB, j);
        Oa[j] = __shfl_sync(0xffffffffu, expA, 12 + j);
        Ob[j] = __shfl_sync(0xffffffffu, expB, 12 + j);
        Oc[j] = __shfl_sync(0xffffffffu, expC, 12 + j);

        float sx, cx; __sincosf(0.5f * xa[j], &sx, &cx);
        const float v   = 1.f - u;                 // s1^2
        const float f0r = fmaf(u, cx, -w * sx);
        const float f0i = fmaf(v, cx, -w * sx);
        const float f1r = fmaf(w, cx,  u * sx);
        const float f1i = fmaf(-v, sx, -w * cx);
        Aq[j] = fmaf(f0r, f0r, f0i * f0i);
        Bq[j] = fmaf(f1r, f1r, f1i * f1i);
        Gr[j] = fmaf(f0r, f1r, f0i * f1i);         // Re(f0 conj f1)
        Gi[j] = fmaf(f0i, f1r, -f0r * f1i);        // Im(f0 conj f1)
    }

    // ---- serial Hermitian transfer sweep (registers only) ----
    float L00 = 1.f, L11 = 0.f, Pr = 0.f, Pi = 0.f;
    float acc = bias;

    #pragma unroll
    for (int j = 0; j < 12; j++){
        const float A = Aq[j], B = Bq[j], gr = Gr[j], gi = Gi[j];

        if (j > 0){
            const float E = fmaf(4.f * gr, Pr, L00 + L11);
            acc = fmaf(hwa[j-1], E, acc);
        }

        const float u2 = gr * Pr, v2 = gi * Pi;
        const float N00 = fmaf(A, L00, fmaf(B, L11, 2.f * (u2 - v2)));
        const float N11 = fmaf(B, L00, fmaf(A, L11, 2.f * (u2 + v2)));
        const float N01r = fmaf(gr, L00 + L11, (A + B) * Pr);
        const float N01i = fmaf(gi, L00 - L11, (A - B) * Pi);

        const float a = Oa[j], bb = Ob[j], cc = Oc[j];
        L00 =  cc * N00;
        L11 = -cc * N11;
        Pr  = fmaf(a, N01r, -bb * N01i);
        Pi  = fmaf(a, N01i,  bb * N01r);
    }

    const float E11 = L00 + L11 + 2.f * Pr;   // empty suffix (X_12 = 1)
    acc = fmaf(hwa[11], E11, acc);

    out[b] = acc;
}

extern "C" void kernel_launch(void* const* d_in, const int* in_sizes, int n_in,
                              void* d_out, int out_size)
{
    const float* x      = (const float*)d_in[0];   // [8192,12]
    const float* params = (const float*)d_in[1];   // [2,12]
    const float* hw     = (const float*)d_in[2];   // [1,12]
    const float* hb     = (const float*)d_in[3];   // [1]
    float* out          = (float*)d_out;           // [8192,1]
    (void)in_sizes; (void)n_in; (void)out_size;

    qexp_kernel<<<BATCH / NT, NT>>>(x, params, hw, hb, out);
}

// round 9
// speedup vs baseline: 1.0606x; 1.0606x over previous
#include <cuda_runtime.h>

#define NT    64
#define BATCH 8192

// Per sample: E_w = <Phi| (⊗_{j<=w} O_j) |Phi>,  Phi = CNOT-chain |⊗ phi_j>
// (bond-2 MPS).  O_j = cos^2(t) Z + sin(t)cos(t) Y - sin(t) X, t = params[1][j].
// phi_j = RY(t1) RX(t1) RY(x_j)|0>, t1 = params[0][j].
// Hermitian boundary: L00, L11 real, P = L01 complex.
//   A=|f0|^2, B=|f1|^2, g=f0*conj(f1)
//   N00 = A L00 + B L11 + 2(gr Pr - gi Pi)
//   N11 = B L00 + A L11 + 2(gr Pr + gi Pi)
//   N01 = ( gr(L00+L11) + (A+B) Pr ,  gi(L00-L11) + (A-B) Pi )
//   L00' = cc N00,  L11' = -cc N11,  P' = (a + i b) N01
// with a=-sin t, b=sin t cos t, cc=cos^2 t.
// Emission: E_{j-1} = (L00+L11) + 4 gr_j Pr;  final E_11 = L00 + L11 + 2 Pr.
__global__ void __launch_bounds__(NT)
qexp_kernel(const float* __restrict__ x, const float* __restrict__ params,
            const float* __restrict__ hw, const float* __restrict__ hb,
            float* __restrict__ out)
{
    const int b = blockIdx.x * NT + threadIdx.x;

    // ---- issue ALL loads up front (one memory epoch, MLP ~13) ----
    const float4* xv = (const float4*)(x + b * 12);       // 48B row, 16B aligned
    const float4 xq0 = xv[0], xq1 = xv[1], xq2 = xv[2];
    const float4* pv = (const float4*)params;             // 24 floats (broadcast)
    const float4 p0 = pv[0], p1 = pv[1], p2 = pv[2];
    const float4 p3 = pv[3], p4 = pv[4], p5 = pv[5];
    const float4* wv = (const float4*)hw;                 // 12 floats (broadcast)
    const float4 w0 = wv[0], w1 = wv[1], w2 = wv[2];
    const float bias = hb[0];

    const float xa[12]  = { xq0.x,xq0.y,xq0.z,xq0.w, xq1.x,xq1.y,xq1.z,xq1.w,
                            xq2.x,xq2.y,xq2.z,xq2.w };
    const float th1[12] = { p0.x,p0.y,p0.z,p0.w, p1.x,p1.y,p1.z,p1.w,
                            p2.x,p2.y,p2.z,p2.w };
    const float th2[12] = { p3.x,p3.y,p3.z,p3.w, p4.x,p4.y,p4.z,p4.w,
                            p5.x,p5.y,p5.z,p5.w };
    const float hwa[12] = { w0.x,w0.y,w0.z,w0.w, w1.x,w1.y,w1.z,w1.w,
                            w2.x,w2.y,w2.z,w2.w };

    // ---- per-wire independent precompute (MUFU-pipelined, high ILP) ----
    float Aq[12], Bq[12], Gr[12], Gi[12], Oa[12], Ob[12], Oc[12];
    #pragma unroll
    for (int j = 0; j < 12; j++){
        float s1, c1; __sincosf(0.5f * th1[j], &s1, &c1);
        float s2, c2; __sincosf(th2[j], &s2, &c2);        // full angle for O
        Oa[j] = -s2; Ob[j] = s2 * c2; Oc[j] = c2 * c2;
        float sx, cx; __sincosf(0.5f * xa[j], &sx, &cx);

        const float u = c1 * c1;            // cos^2(t1/2)
        const float v = 1.f - u;            // sin^2(t1/2)
        const float w = c1 * s1;            // cos*sin
        // phi_j = RY(t1) RX(t1) (cx, sx)
        const float f0r = fmaf(u, cx, -w * sx);
        const float f0i = fmaf(v, cx, -w * sx);
        const float f1r = fmaf(w, cx,  u * sx);
        const float f1i = fmaf(-v, sx, -w * cx);
        Aq[j] = fmaf(f0r, f0r, f0i * f0i);
        Bq[j] = fmaf(f1r, f1r, f1i * f1i);
        Gr[j] = fmaf(f0r, f1r, f0i * f1i);   // Re(f0 conj f1)
        Gi[j] = fmaf(f0i, f1r, -f0r * f1i);  // Im(f0 conj f1)
    }

    // ---- serial Hermitian transfer sweep (registers only) ----
    float L00 = 1.f, L11 = 0.f, Pr = 0.f, Pi = 0.f;
    float acc = bias;

    #pragma unroll
    for (int j = 0; j < 12; j++){
        const float A = Aq[j], B = Bq[j], gr = Gr[j], gi = Gi[j];

        if (j > 0){
            const float E = fmaf(4.f * gr, Pr, L00 + L11);
            acc = fmaf(hwa[j-1], E, acc);
        }

        const float u2 = gr * Pr, v2 = gi * Pi;
        const float N00 = fmaf(A, L00, fmaf(B, L11, 2.f * (u2 - v2)));
        const float N11 = fmaf(B, L00, fmaf(A, L11, 2.f * (u2 + v2)));
        const float N01r = fmaf(gr, L00 + L11, (A + B) * Pr);
        const float N01i = fmaf(gi, L00 - L11, (A - B) * Pi);

        const float a = Oa[j], bb = Ob[j], cc = Oc[j];
        L00 =  cc * N00;
        L11 = -cc * N11;
        Pr  = fmaf(a, N01r, -bb * N01i);
        Pi  = fmaf(a, N01i,  bb * N01r);
    }

    const float E11 = L00 + L11 + 2.f * Pr;   // empty suffix (X_12 = 1)
    acc = fmaf(hwa[11], E11, acc);

    out[b] = acc;
}

extern "C" void kernel_launch(void* const* d_in, const int* in_sizes, int n_in,
                              void* d_out, int out_size)
{
    const float* x      = (const float*)d_in[0];   // [8192,12]
    const float* params = (const float*)d_in[1];   // [2,12]
    const float* hw     = (const float*)d_in[2];   // [1,12]
    const float* hb     = (const float*)d_in[3];   // [1]
    float* out          = (float*)d_out;           // [8192,1]
    (void)in_sizes; (void)n_in; (void)out_size;

    qexp_kernel<<<BATCH / NT, NT>>>(x, params, hw, hb, out);
}